// round 15
// baseline (speedup 1.0000x reference)
#include <cuda_runtime.h>
#include <cuda_bf16.h>

// LIF neuron forward over T=16 timesteps.
// x: [B=16, C=64, T=16, H=64, W=64] fp32, decay: [1] fp32.
//   mem_t = mem_{t-1} * sigmoid(decay) * (1 - spike_{t-1}) + x_t
//   spike_t = (mem_t > 0.5) ? 1 : 0
//
// Pure HBM-streaming kernel at the LTS/DRAM floor (~6.25 TB/s). Record
// config: 16-deep LDG.128.CS batch / STG.128.CS burst, 128-thr CTAs
// (82.05 us, 4x reproduced). This round: same 256 B-per-thread burst
// geometry expressed as sm_103a 256-bit ops (ld/st.global.cs.v8.f32) —
// 8 timesteps x 32 B per phase, two phases — halving LSU request count
// per byte to relieve L1tex wavefront-queue pressure.

#define T_STEPS 16
#define HW 4096                    // 64*64
#define BC 1024                    // 16*64
#define V8_PER_PLANE (HW / 8)      // 512 x 8-float groups per (bc,t) plane
#define BLOCK 128
#define TBATCH 8

__device__ __forceinline__ void ldg256_cs(float4& a, float4& b, const float* p) {
    asm volatile(
        "ld.global.cs.v8.f32 {%0,%1,%2,%3,%4,%5,%6,%7}, [%8];"
        : "=f"(a.x), "=f"(a.y), "=f"(a.z), "=f"(a.w),
          "=f"(b.x), "=f"(b.y), "=f"(b.z), "=f"(b.w)
        : "l"(p));
}

__device__ __forceinline__ void stg256_cs(float* p, const float4& a, const float4& b) {
    asm volatile(
        "st.global.cs.v8.f32 [%0], {%1,%2,%3,%4,%5,%6,%7,%8};"
        :: "l"(p),
           "f"(a.x), "f"(a.y), "f"(a.z), "f"(a.w),
           "f"(b.x), "f"(b.y), "f"(b.z), "f"(b.w)
        : "memory");
}

__global__ __launch_bounds__(BLOCK) void lif_kernel(
    const float* __restrict__ x,
    const float* __restrict__ decay,
    float* __restrict__ out)
{
    const float d  = decay[0];
    const float ds = 1.0f / (1.0f + __expf(-d));

    const unsigned g  = blockIdx.x * BLOCK + threadIdx.x;
    const unsigned bc = g >> 9;         // which (b,c) slab (512 groups/plane)
    const unsigned s8 = g & 511u;       // which 8-float group within the plane

    const size_t base = (size_t)bc * (T_STEPS * HW) + (size_t)s8 * 8;

    const float* __restrict__ xin  = x + base;
    float* __restrict__ xout = out + base;

    float4 memA = make_float4(0.f, 0.f, 0.f, 0.f);
    float4 memB = make_float4(0.f, 0.f, 0.f, 0.f);
    float4 spkA = make_float4(0.f, 0.f, 0.f, 0.f);
    float4 spkB = make_float4(0.f, 0.f, 0.f, 0.f);

#pragma unroll
    for (int tb = 0; tb < T_STEPS; tb += TBATCH) {
        // ---- read burst: 8 independent 256-bit streaming loads ----
        float4 xa[TBATCH], xb[TBATCH];
#pragma unroll
        for (int j = 0; j < TBATCH; j++)
            ldg256_cs(xa[j], xb[j], xin + (size_t)(tb + j) * HW);

        // ---- recurrence for this batch ----
        float4 sa[TBATCH], sb[TBATCH];
#pragma unroll
        for (int j = 0; j < TBATCH; j++) {
            memA.x = memA.x * ds * (1.0f - spkA.x) + xa[j].x;
            memA.y = memA.y * ds * (1.0f - spkA.y) + xa[j].y;
            memA.z = memA.z * ds * (1.0f - spkA.z) + xa[j].z;
            memA.w = memA.w * ds * (1.0f - spkA.w) + xa[j].w;
            memB.x = memB.x * ds * (1.0f - spkB.x) + xb[j].x;
            memB.y = memB.y * ds * (1.0f - spkB.y) + xb[j].y;
            memB.z = memB.z * ds * (1.0f - spkB.z) + xb[j].z;
            memB.w = memB.w * ds * (1.0f - spkB.w) + xb[j].w;

            spkA.x = (memA.x > 0.5f) ? 1.0f : 0.0f;
            spkA.y = (memA.y > 0.5f) ? 1.0f : 0.0f;
            spkA.z = (memA.z > 0.5f) ? 1.0f : 0.0f;
            spkA.w = (memA.w > 0.5f) ? 1.0f : 0.0f;
            spkB.x = (memB.x > 0.5f) ? 1.0f : 0.0f;
            spkB.y = (memB.y > 0.5f) ? 1.0f : 0.0f;
            spkB.z = (memB.z > 0.5f) ? 1.0f : 0.0f;
            spkB.w = (memB.w > 0.5f) ? 1.0f : 0.0f;

            sa[j] = spkA;
            sb[j] = spkB;
        }

        // ---- write burst: 8 256-bit streaming stores ----
#pragma unroll
        for (int j = 0; j < TBATCH; j++)
            stg256_cs(xout + (size_t)(tb + j) * HW, sa[j], sb[j]);
    }
}

extern "C" void kernel_launch(void* const* d_in, const int* in_sizes, int n_in,
                              void* d_out, int out_size)
{
    const float* x     = (const float*)d_in[0];
    const float* decay = (const float*)d_in[1];
    float* out = (float*)d_out;

    const int blocks = (BC * V8_PER_PLANE) / BLOCK;  // 4096
    lif_kernel<<<blocks, BLOCK>>>(x, decay, out);
}

// round 16
// speedup vs baseline: 1.0254x; 1.0254x over previous
#include <cuda_runtime.h>
#include <cuda_bf16.h>

// LIF neuron forward over T=16 timesteps. FINAL KERNEL.
// Session-converged after 15 rounds; reproduced at 82.05/82.37/82.05 us
// (all alternatives: 82.3-86.8 us).
//
// x: [B=16, C=64, T=16, H=64, W=64] fp32, decay: [1] fp32.
// out[b,c,t,h,w] = spike_t where:
//   mem_t = mem_{t-1} * sigmoid(decay) * (1 - spike_{t-1}) + x_t
//   spike_t = (mem_t > 0.5) ? 1 : 0
// (output clip is identity since spike in {0,1})
//
// Pure HBM-streaming kernel: 512 MB contractually irreducible traffic at
// ~6.25 TB/s — the B300's measured path-independent LTS/DRAM ceiling.
// Converged configuration and the evidence behind each choice:
//   - 16-deep front-batched LDG.128.CS: .cs is load-bearing twice over —
//     it marks the stream evict-first in L2 AND prevents ptxas from
//     collapsing the batch back into an interleaved schedule (regs 80).
//     Shallow batches (1/2/4/8) and plain loads all measured slower.
//   - sequential LIF recurrence on registers (compute pipes ~6% busy).
//   - 16-deep STG.128.CS write burst (.wt write-through and plain stores
//     both measured slower; .wt defeats L2 write coalescing).
//   - 128-thread CTAs, 8192 blocks: granularity optimum (64 and 256 both
//     measured slower at identical warps/SM). Occupancy ~33% is
//     non-binding (tested 31-91%, no effect).
//   - flat grid (persistent grid-stride measured slower).
//   - 128-bit ops (256-bit v8 measured slower: LTS is byte-capped, not
//     request-capped).

#define T_STEPS 16
#define HW 4096                    // 64*64
#define BC 1024                    // 16*64
#define VEC4_PER_PLANE (HW / 4)    // 1024 float4 per (bc,t) plane
#define BLOCK 128

__global__ __launch_bounds__(BLOCK) void lif_kernel(
    const float* __restrict__ x,
    const float* __restrict__ decay,
    float* __restrict__ out)
{
    const float d  = decay[0];
    const float ds = 1.0f / (1.0f + __expf(-d));

    const unsigned g  = blockIdx.x * BLOCK + threadIdx.x;
    const unsigned bc = g >> 10;        // which (b,c) slab
    const unsigned s4 = g & 1023u;      // which float4 within the HW plane

    const size_t base = (size_t)bc * (T_STEPS * HW) + (size_t)s4 * 4;

    const float4* __restrict__ xin  = (const float4*)(x + base);
    float4* __restrict__ xout = (float4*)(out + base);

    // ---- phase 1: batch all 16 independent streaming loads (MLP=16) ----
    float4 xv[T_STEPS];
#pragma unroll
    for (int t = 0; t < T_STEPS; t++) {
        xv[t] = __ldcs(&xin[(size_t)t * VEC4_PER_PLANE]);
    }

    // ---- phase 2: sequential recurrence + streaming store burst ----
    float4 mem = make_float4(0.f, 0.f, 0.f, 0.f);
    float4 spk = make_float4(0.f, 0.f, 0.f, 0.f);

#pragma unroll
    for (int t = 0; t < T_STEPS; t++) {
        mem.x = mem.x * ds * (1.0f - spk.x) + xv[t].x;
        mem.y = mem.y * ds * (1.0f - spk.y) + xv[t].y;
        mem.z = mem.z * ds * (1.0f - spk.z) + xv[t].z;
        mem.w = mem.w * ds * (1.0f - spk.w) + xv[t].w;

        spk.x = (mem.x > 0.5f) ? 1.0f : 0.0f;
        spk.y = (mem.y > 0.5f) ? 1.0f : 0.0f;
        spk.z = (mem.z > 0.5f) ? 1.0f : 0.0f;
        spk.w = (mem.w > 0.5f) ? 1.0f : 0.0f;

        __stcs(&xout[(size_t)t * VEC4_PER_PLANE], spk);
    }
}

extern "C" void kernel_launch(void* const* d_in, const int* in_sizes, int n_in,
                              void* d_out, int out_size)
{
    const float* x     = (const float*)d_in[0];
    const float* decay = (const float*)d_in[1];
    float* out = (float*)d_out;

    const int blocks = (BC * VEC4_PER_PLANE) / BLOCK;  // 8192
    lif_kernel<<<blocks, BLOCK>>>(x, decay, out);
}